// round 10
// baseline (speedup 1.0000x reference)
#include <cuda_runtime.h>
#include <stdint.h>

// LSTM: H=50, input 1, T=1024, B independent batch elements.
// R=2 row-blocking x M=2 weight-shared batches (R9 winner), now with the
// gate exchange fused into phase 1 via a lane-pair shuffle -> ONE barrier
// per timestep and no p_sh traffic.
//   thread 2j   (even lane): rows j      (i-gate), j+100 (g-gate)
//   thread 2j+1 (odd  lane): rows j+50   (f-gate), j+150 (o-gate)
// Even lane computes p = sig(i)*tanh(g); shfl_xor(1) hands it to the odd
// lane, which holds c privately: c = sig(f)*c + p; h = sig(o)*tanh(c),
// written to double-buffered h_sh. Activations via MUFU tanh.approx.f32.
// Per thread per step: 26 broadcast LDS.128 + 104 fma.rn.f32x2 + 2 shfl.
// Gate order (PyTorch): i[0:50], f[50:100], g[100:150], o[150:200].

#define HH 50
#define TT 1024
#define BT 128

typedef unsigned long long ull;

__device__ __forceinline__ float tanha(float x) {
    float y;
    asm("tanh.approx.f32 %0, %1;" : "=f"(y) : "f"(x));
    return y;
}
__device__ __forceinline__ float sigt(float x) {
    return fmaf(0.5f, tanha(0.5f * x), 0.5f);   // sigmoid via tanh
}
__device__ __forceinline__ void fma2(ull& d, ull a, ull b) {
    asm("fma.rn.f32x2 %0, %1, %2, %0;" : "+l"(d) : "l"(a), "l"(b));
}
__device__ __forceinline__ void add2(ull& d, ull a) {
    asm("add.rn.f32x2 %0, %0, %1;" : "+l"(d) : "l"(a));
}
__device__ __forceinline__ ull pack2(float lo, float hi) {
    return ((ull)__float_as_uint(hi) << 32) | (ull)__float_as_uint(lo);
}
__device__ __forceinline__ float sum2(ull a) {
    return __uint_as_float((unsigned)a) + __uint_as_float((unsigned)(a >> 32));
}

__global__ void __launch_bounds__(BT, 3)
lstm_kernel(const float* __restrict__ x,      // [B, T, 1]
            const float* __restrict__ W_ih,   // [200, 1]
            const float* __restrict__ W_hh,   // [200, 50]
            const float* __restrict__ b_ih,   // [200]
            const float* __restrict__ b_hh,   // [200]
            const float* __restrict__ W_lin,  // [1, 50]
            const float* __restrict__ b_lin,  // [1]
            float* __restrict__ out,          // [B, 1]
            int B)
{
    __shared__ __align__(16) float h_sh[2][2][56];  // [batch][buf][idx]
    __shared__ float x_sh[2][TT];

    const int tid = threadIdx.x;
    const int b0  = blockIdx.x * 2;
    const int jj  = tid >> 1;            // hidden index 0..63
    const int odd = tid & 1;             // 0: (i,g)   1: (f,o)
    const bool active = (jj < HH);

    for (int i = tid; i < 2 * TT; i += BT) {
        const int m = i >> 10, t = i & (TT - 1);
        x_sh[m][t] = (b0 + m < B) ? x[(size_t)(b0 + m) * TT + t] : 0.0f;
    }
    for (int i = tid; i < 2 * 2 * 56; i += BT) ((float*)h_sh)[i] = 0.0f;

    // Rows: rA = i or f, rB = g or o (zero weights if inactive).
    const int rA = jj + odd * 50;
    const int rB = rA + 100;
    ull wA[26], wB[26];
    float wihA = 0.0f, wihB = 0.0f, biasA = 0.0f, biasB = 0.0f;
    if (active) {
        wihA  = W_ih[rA];            wihB  = W_ih[rB];
        biasA = b_ih[rA] + b_hh[rA]; biasB = b_ih[rB] + b_hh[rB];
    }
    #pragma unroll
    for (int q = 0; q < 26; q++) {
        float l0 = (active && 2 * q     < HH) ? W_hh[rA * HH + 2 * q]     : 0.0f;
        float l1 = (active && 2 * q + 1 < HH) ? W_hh[rA * HH + 2 * q + 1] : 0.0f;
        float m0 = (active && 2 * q     < HH) ? W_hh[rB * HH + 2 * q]     : 0.0f;
        float m1 = (active && 2 * q + 1 < HH) ? W_hh[rB * HH + 2 * q + 1] : 0.0f;
        wA[q] = pack2(l0, l1);
        wB[q] = pack2(m0, m1);
    }
    float c0 = 0.0f, c1 = 0.0f;          // cell state, odd lanes
    __syncthreads();

    #pragma unroll 1
    for (int t = 0; t < TT; t++) {
        const int rb = t & 1;
        const float xt0 = x_sh[0][t];
        const float xt1 = x_sh[1][t];
        ull aA0 = (ull)__float_as_uint(fmaf(xt0, wihA, biasA)), aA0b = 0ull;
        ull aB0 = (ull)__float_as_uint(fmaf(xt0, wihB, biasB)), aB0b = 0ull;
        ull aA1 = (ull)__float_as_uint(fmaf(xt1, wihA, biasA)), aA1b = 0ull;
        ull aB1 = (ull)__float_as_uint(fmaf(xt1, wihB, biasB)), aB1b = 0ull;
        const ulonglong2* h20 = (const ulonglong2*)h_sh[0][rb];
        const ulonglong2* h21 = (const ulonglong2*)h_sh[1][rb];
        #pragma unroll
        for (int q = 0; q < 13; q++) {
            ulonglong2 hv0 = h20[q];               // broadcast LDS.128
            fma2(aA0,  wA[2 * q],     hv0.x);
            fma2(aA0b, wA[2 * q + 1], hv0.y);
            fma2(aB0,  wB[2 * q],     hv0.x);
            fma2(aB0b, wB[2 * q + 1], hv0.y);
            ulonglong2 hv1 = h21[q];
            fma2(aA1,  wA[2 * q],     hv1.x);
            fma2(aA1b, wA[2 * q + 1], hv1.y);
            fma2(aB1,  wB[2 * q],     hv1.x);
            fma2(aB1b, wB[2 * q + 1], hv1.y);
        }
        add2(aA0, aA0b);  add2(aB0, aB0b);
        add2(aA1, aA1b);  add2(aB1, aB1b);
        const float sA0 = sum2(aA0);   // i or f, batch 0
        const float sB0 = sum2(aB0);   // g or o, batch 0
        const float sA1 = sum2(aA1);   // i or f, batch 1
        const float sB1 = sum2(aB1);   // g or o, batch 1
        const float act0_0 = sigt(sA0);                        // sig(i)/sig(f)
        const float act0_1 = sigt(sA1);
        const float act1_0 = odd ? sigt(sB0) : tanha(sB0);     // sig(o)/tanh(g)
        const float act1_1 = odd ? sigt(sB1) : tanha(sB1);
        // Even lane: p = sig(i)*tanh(g); hand to odd lane via 1 shfl.
        const float p0 = act0_0 * act1_0;
        const float p1 = act0_1 * act1_1;
        const float q0 = __shfl_xor_sync(0xFFFFFFFFu, p0, 1);
        const float q1 = __shfl_xor_sync(0xFFFFFFFFu, p1, 1);
        if (odd & (int)active) {
            c0 = fmaf(act0_0, c0, q0);             // sig(f)*c + sig(i)*tanh(g)
            c1 = fmaf(act0_1, c1, q1);
            h_sh[0][rb ^ 1][jj] = act1_0 * tanha(c0);   // sig(o)*tanh(c)
            h_sh[1][rb ^ 1][jj] = act1_1 * tanha(c1);
        }
        __syncthreads();
    }

    // Final h in buffer (1023&1)^1 == 0. Linear head, one thread per batch.
    if (tid < 2 && b0 + tid < B) {
        float s = b_lin[0];
        #pragma unroll 1
        for (int k = 0; k < HH; k++) s = fmaf(h_sh[tid][0][k], W_lin[k], s);
        out[b0 + tid] = s;
    }
}

extern "C" void kernel_launch(void* const* d_in, const int* in_sizes, int n_in,
                              void* d_out, int out_size) {
    const float* x     = (const float*)d_in[0];
    const float* W_ih  = (const float*)d_in[1];
    const float* W_hh  = (const float*)d_in[2];
    const float* b_ih  = (const float*)d_in[3];
    const float* b_hh  = (const float*)d_in[4];
    const float* W_lin = (const float*)d_in[5];
    const float* b_lin = (const float*)d_in[6];
    float* out = (float*)d_out;

    int B = in_sizes[0] / TT;
    int grid = (B + 1) / 2;
    lstm_kernel<<<grid, BT>>>(x, W_ih, W_hh, b_ih, b_hh, W_lin, b_lin, out, B);
}

// round 11
// speedup vs baseline: 1.0226x; 1.0226x over previous
#include <cuda_runtime.h>
#include <stdint.h>

// LSTM: H=50, input 1, T=1024, B independent batch elements.
// R=2 row-blocking x M=3 weight-shared batches, folded accumulator chains.
//   thread 2j   (even lane): rows j    (i-gate), j+100 (g-gate)
//   thread 2j+1 (odd  lane): rows j+50 (f-gate), j+150 (o-gate)
// Per thread per step: 39 broadcast LDS.128 + 156 fma.rn.f32x2 (6 chains,
// depth 26) + 3 shfl. Even lane computes p = sig(i)*tanh(g); shfl_xor(1)
// hands it to the odd lane, which holds c privately and writes h to the
// double-buffered h_sh. ONE __syncthreads per timestep.
// Activations via MUFU tanh.approx.f32 (sigmoid = 0.5*tanh(x/2)+0.5).
// Gate order (PyTorch): i[0:50], f[50:100], g[100:150], o[150:200].

#define HH 50
#define TT 1024
#define BT 128
#define MM 3

typedef unsigned long long ull;

__device__ __forceinline__ float tanha(float x) {
    float y;
    asm("tanh.approx.f32 %0, %1;" : "=f"(y) : "f"(x));
    return y;
}
__device__ __forceinline__ float sigt(float x) {
    return fmaf(0.5f, tanha(0.5f * x), 0.5f);   // sigmoid via tanh
}
__device__ __forceinline__ void fma2(ull& d, ull a, ull b) {
    asm("fma.rn.f32x2 %0, %1, %2, %0;" : "+l"(d) : "l"(a), "l"(b));
}
__device__ __forceinline__ ull pack2(float lo, float hi) {
    return ((ull)__float_as_uint(hi) << 32) | (ull)__float_as_uint(lo);
}
__device__ __forceinline__ float sum2(ull a) {
    return __uint_as_float((unsigned)a) + __uint_as_float((unsigned)(a >> 32));
}

__global__ void __launch_bounds__(BT, 3)
lstm_kernel(const float* __restrict__ x,      // [B, T, 1]
            const float* __restrict__ W_ih,   // [200, 1]
            const float* __restrict__ W_hh,   // [200, 50]
            const float* __restrict__ b_ih,   // [200]
            const float* __restrict__ b_hh,   // [200]
            const float* __restrict__ W_lin,  // [1, 50]
            const float* __restrict__ b_lin,  // [1]
            float* __restrict__ out,          // [B, 1]
            int B)
{
    __shared__ __align__(16) float h_sh[MM][2][56];  // [batch][buf][idx]
    __shared__ float x_sh[MM][TT];

    const int tid = threadIdx.x;
    const int b0  = blockIdx.x * MM;
    const int jj  = tid >> 1;            // hidden index 0..63
    const int odd = tid & 1;             // 0: (i,g)   1: (f,o)
    const bool active = (jj < HH);

    for (int i = tid; i < MM * TT; i += BT) {
        const int m = i >> 10, t = i & (TT - 1);
        x_sh[m][t] = (b0 + m < B) ? x[(size_t)(b0 + m) * TT + t] : 0.0f;
    }
    for (int i = tid; i < MM * 2 * 56; i += BT) ((float*)h_sh)[i] = 0.0f;

    // Rows: rA = i or f, rB = g or o (zero weights if inactive).
    const int rA = jj + odd * 50;
    const int rB = rA + 100;
    ull wA[26], wB[26];
    float wihA = 0.0f, wihB = 0.0f, biasA = 0.0f, biasB = 0.0f;
    if (active) {
        wihA  = W_ih[rA];            wihB  = W_ih[rB];
        biasA = b_ih[rA] + b_hh[rA]; biasB = b_ih[rB] + b_hh[rB];
    }
    #pragma unroll
    for (int q = 0; q < 26; q++) {
        float l0 = (active && 2 * q     < HH) ? W_hh[rA * HH + 2 * q]     : 0.0f;
        float l1 = (active && 2 * q + 1 < HH) ? W_hh[rA * HH + 2 * q + 1] : 0.0f;
        float m0 = (active && 2 * q     < HH) ? W_hh[rB * HH + 2 * q]     : 0.0f;
        float m1 = (active && 2 * q + 1 < HH) ? W_hh[rB * HH + 2 * q + 1] : 0.0f;
        wA[q] = pack2(l0, l1);
        wB[q] = pack2(m0, m1);
    }
    float c[MM];
    #pragma unroll
    for (int m = 0; m < MM; m++) c[m] = 0.0f;    // cell state, odd lanes
    __syncthreads();

    #pragma unroll 1
    for (int t = 0; t < TT; t++) {
        const int rb = t & 1;
        ull aA[MM], aB[MM];
        #pragma unroll
        for (int m = 0; m < MM; m++) {
            const float xt = x_sh[m][t];
            aA[m] = (ull)__float_as_uint(fmaf(xt, wihA, biasA));  // hi = +0
            aB[m] = (ull)__float_as_uint(fmaf(xt, wihB, biasB));
        }
        const ulonglong2* h2[MM];
        #pragma unroll
        for (int m = 0; m < MM; m++)
            h2[m] = (const ulonglong2*)h_sh[m][rb];
        #pragma unroll
        for (int q = 0; q < 13; q++) {
            #pragma unroll
            for (int m = 0; m < MM; m++) {
                ulonglong2 hv = h2[m][q];          // broadcast LDS.128
                fma2(aA[m], wA[2 * q],     hv.x);  // folded chain (depth 26)
                fma2(aA[m], wA[2 * q + 1], hv.y);
                fma2(aB[m], wB[2 * q],     hv.x);
                fma2(aB[m], wB[2 * q + 1], hv.y);
            }
        }
        #pragma unroll
        for (int m = 0; m < MM; m++) {
            const float sA = sum2(aA[m]);          // i or f
            const float sB = sum2(aB[m]);          // g or o
            const float act0 = sigt(sA);                       // sig(i)/sig(f)
            const float act1 = odd ? sigt(sB) : tanha(sB);     // sig(o)/tanh(g)
            const float p = act0 * act1;           // even lane: sig(i)*tanh(g)
            const float q2 = __shfl_xor_sync(0xFFFFFFFFu, p, 1);
            if (odd & (int)active) {
                c[m] = fmaf(act0, c[m], q2);       // sig(f)*c + sig(i)*tanh(g)
                h_sh[m][rb ^ 1][jj] = act1 * tanha(c[m]);   // sig(o)*tanh(c)
            }
        }
        __syncthreads();
    }

    // Final h in buffer (1023&1)^1 == 0. Linear head, one thread per batch.
    if (tid < MM && b0 + tid < B) {
        float s = b_lin[0];
        #pragma unroll 1
        for (int k = 0; k < HH; k++) s = fmaf(h_sh[tid][0][k], W_lin[k], s);
        out[b0 + tid] = s;
    }
}

extern "C" void kernel_launch(void* const* d_in, const int* in_sizes, int n_in,
                              void* d_out, int out_size) {
    const float* x     = (const float*)d_in[0];
    const float* W_ih  = (const float*)d_in[1];
    const float* W_hh  = (const float*)d_in[2];
    const float* b_ih  = (const float*)d_in[3];
    const float* b_hh  = (const float*)d_in[4];
    const float* W_lin = (const float*)d_in[5];
    const float* b_lin = (const float*)d_in[6];
    float* out = (float*)d_out;

    int B = in_sizes[0] / TT;
    int grid = (B + MM - 1) / MM;
    lstm_kernel<<<grid, BT>>>(x, W_ih, W_hh, b_ih, b_hh, W_lin, b_lin, out, B);
}